// round 17
// baseline (speedup 1.0000x reference)
#include <cuda_runtime.h>
#include <cstdint>

// q: (32, 8, 512, 64) f32   k: (32, 8, 64, 512) f32   v: (32, 8, 512, 64) f32
// attn_mask: (8, 512, 512) bool (u8 vs i32, detected inside pack_mask); True => -inf
// out: (32, 8, 512, 64) f32
static constexpr int H_   = 8;
static constexpr int C_   = 4;
static constexpr int L_   = 512;
static constexpr int D_   = 64;
static constexpr int QR   = 128;       // q rows per CTA (8 warps x 16 rows)
static constexpr int KT   = 64;        // keys per chunk
static constexpr int NCH  = L_ / KT;   // 8
static constexpr int NTHR = 256;

// SMEM:
//  Qp[64][68] float2  row-pair packed q: Qp[w*8+rr][c] = (Q[w*16+rr][c], Q[w*16+rr+8][c])
//  Ks[2][64][72] f32  raw k, d-major, double-buffered (cp.async)
//  Vs[2][64][72] f32  raw v, j-major, double-buffered (cp.async); converted
//                     to tf32(rna) in place once per chunk
static constexpr int QP_OFF  = 0;               // in float2 units
static constexpr int QP_F2   = 64 * 68;         // 34816 B
static constexpr int KBUF_F  = 64 * 72;
static constexpr int KS_OFF  = QP_F2 * 2;       // float index after Qp
static constexpr int VS_OFF  = KS_OFF + 2 * KBUF_F;
static constexpr int SMEM_FLOATS = VS_OFF + 2 * KBUF_F;
static constexpr int SMEM_BYTES  = SMEM_FLOATS * 4;   // 108544 B -> 2 CTAs/SM

extern __shared__ float smem_f[];

// Packed mask bits: [b][row][chunk] -> u64, bit j = key (chunk*64+j) masked.
__device__ unsigned long long g_mbits[H_ * L_ * NCH];

// Detects dtype (block-local 8192-word vote) and packs bits.
// int32 bool words are always 0/1; u8 bool words exceed 1 unless the 4-byte
// pattern is (0,0,0,0)/(1,0,0,0) (p=1/8/word) -> P(block miss) = 8^-8192 ~ 0.
__global__ void pack_mask(const unsigned char* __restrict__ M)
{
    __shared__ int blk_u8;
    if (threadIdx.x == 0) blk_u8 = 0;
    __syncthreads();

    int idx = blockIdx.x * blockDim.x + threadIdx.x;   // 0 .. 8*512*8-1
    int ch  = idx & 7;
    int row = idx >> 3;                                // b*512 + l

    const unsigned char* p8 = M + (size_t)row * L_ + ch * 64;
    uint4 w8[4];
    #pragma unroll
    for (int w = 0; w < 4; w++) w8[w] = ((const uint4*)p8)[w];

    int has = 0;
    #pragma unroll
    for (int w = 0; w < 4; w++)
        if (w8[w].x > 1u || w8[w].y > 1u || w8[w].z > 1u || w8[w].w > 1u)
            has = 1;
    if (has) blk_u8 = 1;      // benign race, all writers write 1
    __syncthreads();

    unsigned long long bits = 0ull;
    if (blk_u8) {
        #pragma unroll
        for (int w = 0; w < 4; w++) {
            unsigned int ws[4] = {w8[w].x, w8[w].y, w8[w].z, w8[w].w};
            #pragma unroll
            for (int e = 0; e < 4; e++)
                #pragma unroll
                for (int bq = 0; bq < 4; bq++)
                    if ((ws[e] >> (bq * 8)) & 0xFF)
                        bits |= 1ull << (w * 16 + e * 4 + bq);
        }
    } else {
        const int* p = (const int*)M + (size_t)row * L_ + ch * 64;
        #pragma unroll
        for (int w = 0; w < 16; w++) {
            int4 t = ((const int4*)p)[w];
            if (t.x) bits |= 1ull << (w * 4 + 0);
            if (t.y) bits |= 1ull << (w * 4 + 1);
            if (t.z) bits |= 1ull << (w * 4 + 2);
            if (t.w) bits |= 1ull << (w * 4 + 3);
        }
    }
    g_mbits[idx] = bits;
}

__device__ __forceinline__ float tf32hi(float x) {
    return __uint_as_float(__float_as_uint(x) & 0xFFFFE000u);
}
__device__ __forceinline__ float tf32rna(float x) {
    uint32_t u;
    asm("cvt.rna.tf32.f32 %0, %1;" : "=r"(u) : "f"(x));
    return __uint_as_float(u);
}
__device__ __forceinline__ void mma_tf32(float c[4],
                                         float a0, float a1, float a2, float a3,
                                         float b0, float b1)
{
    asm volatile(
        "mma.sync.aligned.m16n8k8.row.col.f32.tf32.tf32.f32 "
        "{%0,%1,%2,%3}, {%4,%5,%6,%7}, {%8,%9}, {%0,%1,%2,%3};\n"
        : "+f"(c[0]), "+f"(c[1]), "+f"(c[2]), "+f"(c[3])
        : "r"(__float_as_uint(a0)), "r"(__float_as_uint(a1)),
          "r"(__float_as_uint(a2)), "r"(__float_as_uint(a3)),
          "r"(__float_as_uint(b0)), "r"(__float_as_uint(b1)));
}
__device__ __forceinline__ void cp16(uint32_t dst, const void* src)
{
    asm volatile("cp.async.cg.shared.global [%0], [%1], 16;\n"
                 :: "r"(dst), "l"(src));
}

__global__ __launch_bounds__(NTHR, 2)
void attn_fwd_mma5(const float* __restrict__ Q,
                   const float* __restrict__ K,
                   const float* __restrict__ V,
                   float* __restrict__ O)
{
    float2* Qp = (float2*)smem_f;

    const int qt   = blockIdx.x;         // 0..3
    const int gh   = blockIdx.y;         // 0..255
    const int b    = (gh / H_) / C_;
    const int tid  = threadIdx.x;
    const int w    = tid >> 5;           // warp 0..7 -> rows w*16..+15
    const int lane = tid & 31;
    const int rr   = lane >> 2;          // 0..7
    const int cc   = lane & 3;           // 0..3

    uint32_t smem_u32;
    {
        uint32_t a;
        asm("{ .reg .u64 t; cvta.to.shared.u64 t, %1; cvt.u32.u64 %0, t; }"
            : "=r"(a) : "l"(smem_f));
        smem_u32 = a;
    }

    const float* qg = Q + (size_t)gh * L_ * D_;
    const float* kg = K + (size_t)gh * D_ * L_;
    const float* vg = V + (size_t)gh * L_ * D_;

    // ---- prefetch K/V chunk 0 (cp.async), then repack Q via LDG (overlapped)
    {
        #pragma unroll
        for (int it = 0; it < 4; it++) {          // K ch0
            int i = it * NTHR + tid;
            int d = i >> 4;
            int j = (i & 15) * 4;
            cp16(smem_u32 + (KS_OFF + d * 72 + j) * 4,
                 kg + (size_t)d * L_ + j);
        }
        #pragma unroll
        for (int it = 0; it < 4; it++) {          // V ch0
            int i = it * NTHR + tid;
            int j = i >> 4;
            int d = (i & 15) * 4;
            cp16(smem_u32 + (VS_OFF + j * 72 + d) * 4,
                 vg + (size_t)j * D_ + d);
        }
        asm volatile("cp.async.commit_group;\n");

        // Q repack: Qp[rp][c] = (Q[r_lo][c], Q[r_lo+8][c]), rp = (r_lo/16)*8 + r_lo%8
        #pragma unroll
        for (int it = 0; it < 4; it++) {
            int i  = it * NTHR + tid;             // 0..1023
            int rp = i >> 4;                      // 0..63
            int cb = (i & 15) * 4;                // col block of 4
            int r_lo = (rp >> 3) * 16 + (rp & 7);
            const float* src = qg + (size_t)(qt * QR + r_lo) * D_ + cb;
            float4 lo = *(const float4*)(src);
            float4 hi = *(const float4*)(src + 8 * D_);
            float2* dst = Qp + rp * 68 + cb;
            dst[0] = make_float2(lo.x, hi.x);
            dst[1] = make_float2(lo.y, hi.y);
            dst[2] = make_float2(lo.z, hi.z);
            dst[3] = make_float2(lo.w, hi.w);
        }
    }

    float sacc[8][4];
    float oacc[8][4];
    #pragma unroll
    for (int nt = 0; nt < 8; nt++)
        #pragma unroll
        for (int e = 0; e < 4; e++) oacc[nt][e] = 0.f;
    float mrun[2] = {-1e30f, -1e30f};
    float lrun[2] = {0.f, 0.f};
    const float scale = 0.125f;

    const unsigned long long* mrow0 =
        g_mbits + ((size_t)b * L_ + qt * QR + w * 16 + rr) * NCH;
    const unsigned long long* mrow1 = mrow0 + 8 * NCH;   // +8 q rows

    const int src_a = (lane & 28) | (cc >> 1);   // (rr<<2)|(cc>>1)
    const int src_b = src_a + 2;
    const bool oddc = cc & 1;

    // V-convert task for this thread: row tid>>2, 16-col block (tid&3)*16
    const int vc_r  = tid >> 2;
    const int vc_c  = (tid & 3) * 16;

    for (int ch = 0; ch < NCH; ch++) {
        float* Ks = smem_f + KS_OFF + (ch & 1) * KBUF_F;
        float* Vs = smem_f + VS_OFF + (ch & 1) * KBUF_F;

        __syncthreads();   // all warps done reading buf[(ch+1)&1] (prev cur)

        if (ch + 1 < NCH) {          // prefetch next chunk into other buffer
            const int nb = (ch + 1) & 1;
            const int m1 = (ch + 1) * KT;
            #pragma unroll
            for (int it = 0; it < 4; it++) {
                int i = it * NTHR + tid;
                int d = i >> 4;
                int j = (i & 15) * 4;
                cp16(smem_u32 + (KS_OFF + nb * KBUF_F + d * 72 + j) * 4,
                     kg + (size_t)d * L_ + m1 + j);
            }
            #pragma unroll
            for (int it = 0; it < 4; it++) {
                int i = it * NTHR + tid;
                int j = i >> 4;
                int d = (i & 15) * 4;
                cp16(smem_u32 + (VS_OFF + nb * KBUF_F + j * 72 + d) * 4,
                     vg + (size_t)(m1 + j) * D_ + d);
            }
            asm volatile("cp.async.commit_group;\n");
            asm volatile("cp.async.wait_group 1;\n");
        } else {
            asm volatile("cp.async.wait_group 0;\n");
        }
        __syncthreads();   // cur staging visible to all threads

        // ---- convert V to tf32(rna) in place, once per chunk (dedup cvt)
        {
            float* vp = Vs + vc_r * 72 + vc_c;
            #pragma unroll
            for (int g = 0; g < 4; g++) {
                float4 t = *(float4*)(vp + g * 4);
                t.x = tf32rna(t.x); t.y = tf32rna(t.y);
                t.z = tf32rna(t.z); t.w = tf32rna(t.w);
                *(float4*)(vp + g * 4) = t;
            }
        }
        __syncthreads();   // converts visible before any warp's PV reads

        unsigned long long mb0 = mrow0[ch];
        unsigned long long mb1 = mrow1[ch];

        // ---- QK: 2xTF32 (lo*hi + hi*hi); raw operands for hi terms
        //      (HMMA tf32 ingest truncates fp32 -> identical to explicit hi)
        #pragma unroll
        for (int nt = 0; nt < 8; nt++)
            #pragma unroll
            for (int e = 0; e < 4; e++) sacc[nt][e] = 0.f;

        #pragma unroll
        for (int kk = 0; kk < 8; kk++) {
            const int c = kk * 8 + cc;
            float2 a01 = Qp[(w * 8 + rr) * 68 + c];
            float2 a23 = Qp[(w * 8 + rr) * 68 + c + 4];
            float a0 = a01.x, a1 = a01.y, a2 = a23.x, a3 = a23.y;
            float a0l = a0 - tf32hi(a0);
            float a1l = a1 - tf32hi(a1);
            float a2l = a2 - tf32hi(a2);
            float a3l = a3 - tf32hi(a3);
            #pragma unroll
            for (int nt = 0; nt < 8; nt++) {
                float b0 = Ks[(kk * 8 + cc) * 72 + nt * 8 + rr];
                float b1 = Ks[(kk * 8 + cc + 4) * 72 + nt * 8 + rr];
                mma_tf32(sacc[nt], a0l, a1l, a2l, a3l, b0, b1);  // lo*hi
                mma_tf32(sacc[nt], a0,  a1,  a2,  a3,  b0, b1);  // hi*hi
            }
        }

        // ---- mask + scale + online softmax; P kept in sacc (rna-rounded)
        #pragma unroll
        for (int h = 0; h < 2; h++) {
            const unsigned long long mb = h ? mb1 : mb0;
            float mx = -1e30f;
            #pragma unroll
            for (int nt = 0; nt < 8; nt++) {
                int j0 = nt * 8 + 2 * cc;
                float s0 = sacc[nt][h * 2 + 0];
                float s1 = sacc[nt][h * 2 + 1];
                s0 = ((mb >> j0) & 1ull)       ? -1e30f : s0 * scale;
                s1 = ((mb >> (j0 + 1)) & 1ull) ? -1e30f : s1 * scale;
                sacc[nt][h * 2 + 0] = s0;
                sacc[nt][h * 2 + 1] = s1;
                mx = fmaxf(mx, fmaxf(s0, s1));
            }
            mx = fmaxf(mx, __shfl_xor_sync(0xffffffffu, mx, 1, 4));
            mx = fmaxf(mx, __shfl_xor_sync(0xffffffffu, mx, 2, 4));
            float mnew = fmaxf(mrun[h], mx);
            float corr = __expf(mrun[h] - mnew);
            mrun[h] = mnew;
            float ls = 0.f;
            #pragma unroll
            for (int nt = 0; nt < 8; nt++) {
                float p0 = __expf(sacc[nt][h * 2 + 0] - mnew);
                float p1 = __expf(sacc[nt][h * 2 + 1] - mnew);
                ls += p0 + p1;
                sacc[nt][h * 2 + 0] = tf32rna(p0);
                sacc[nt][h * 2 + 1] = tf32rna(p1);
            }
            ls += __shfl_xor_sync(0xffffffffu, ls, 1, 4);
            ls += __shfl_xor_sync(0xffffffffu, ls, 2, 4);
            lrun[h] = lrun[h] * corr + ls;
            #pragma unroll
            for (int nt = 0; nt < 8; nt++) {
                oacc[nt][h * 2 + 0] *= corr;
                oacc[nt][h * 2 + 1] *= corr;
            }
        }

        // ---- PV: out += P x V; P acc-layout -> A-frag via intra-warp shfl
        #pragma unroll
        for (int jj = 0; jj < 8; jj++) {
            float e0 = sacc[jj][0], e1 = sacc[jj][1];
            float e2 = sacc[jj][2], e3 = sacc[jj][3];
            float x00 = __shfl_sync(0xffffffffu, e0, src_a, 32);
            float x01 = __shfl_sync(0xffffffffu, e1, src_a, 32);
            float x10 = __shfl_sync(0xffffffffu, e2, src_a, 32);
            float x11 = __shfl_sync(0xffffffffu, e3, src_a, 32);
            float x20 = __shfl_sync(0xffffffffu, e0, src_b, 32);
            float x21 = __shfl_sync(0xffffffffu, e1, src_b, 32);
            float x30 = __shfl_sync(0xffffffffu, e2, src_b, 32);
            float x31 = __shfl_sync(0xffffffffu, e3, src_b, 32);
            float p0 = oddc ? x01 : x00;   // P[r   ][jj*8+cc]
            float p1 = oddc ? x11 : x10;   // P[r+8 ][jj*8+cc]
            float p2 = oddc ? x21 : x20;   // P[r   ][jj*8+cc+4]
            float p3 = oddc ? x31 : x30;   // P[r+8 ][jj*8+cc+4]
            #pragma unroll
            for (int nt = 0; nt < 8; nt++) {
                float b0 = Vs[(jj * 8 + cc) * 72 + nt * 8 + rr];      // pre-cvt
                float b1 = Vs[(jj * 8 + cc + 4) * 72 + nt * 8 + rr];  // pre-cvt
                mma_tf32(oacc[nt], p0, p1, p2, p3, b0, b1);
            }
        }
    }

    // ---- epilogue: normalize + store
    #pragma unroll
    for (int h = 0; h < 2; h++) {
        float inv = 1.f / lrun[h];
        int grow = qt * QR + w * 16 + h * 8 + rr;
        float* og = O + ((size_t)gh * L_ + grow) * D_;
        #pragma unroll
        for (int nt = 0; nt < 8; nt++) {
            float2 t;
            t.x = oacc[nt][h * 2 + 0] * inv;
            t.y = oacc[nt][h * 2 + 1] * inv;
            *(float2*)(og + nt * 8 + 2 * cc) = t;
        }
    }
}

extern "C" void kernel_launch(void* const* d_in, const int* in_sizes, int n_in,
                              void* d_out, int out_size)
{
    const float* q = (const float*)d_in[0];
    const float* k = (const float*)d_in[1];
    const float* v = (const float*)d_in[2];
    const unsigned char* m = (const unsigned char*)d_in[3];
    float* o = (float*)d_out;

    cudaFuncSetAttribute(attn_fwd_mma5,
                         cudaFuncAttributeMaxDynamicSharedMemorySize,
                         SMEM_BYTES);

    pack_mask<<<(H_ * L_ * NCH) / 256, 256>>>(m);

    dim3 grid(L_ / QR, 32 * H_);   // (4, 256)
    attn_fwd_mma5<<<grid, NTHR, SMEM_BYTES>>>(q, k, v, o);
}